// round 7
// baseline (speedup 1.0000x reference)
#include <cuda_runtime.h>
#include <mma.h>

using namespace nvcuda;

#define SCALE 0.17677669529663687f  // 1/sqrt(32)

__device__ float g_relbias[4 * 64 * 64];
__device__ float g_wts[65536];   // tf32-rounded [Wq | Wk | Wv | Wo], each 16384
__device__ float g_qh[67108864]; // [8192][64][128] scaled+biased+rounded
__device__ float g_k [67108864];
__device__ float g_v [67108864];
__device__ float g_x [67108864]; // attn output (pre out-proj), tf32-rounded

__device__ __forceinline__ float rnd32(float x) {
    float r;
    asm("cvt.rna.tf32.f32 %0, %1;" : "=f"(r) : "f"(x));
    return r;
}

__global__ void relbias_kernel(const float* __restrict__ bias_table) {
    int idx = blockIdx.x * blockDim.x + threadIdx.x;
    if (idx < 4 * 64 * 64) {
        int h = idx >> 12;
        int n = (idx >> 6) & 63;
        int m = idx & 63;
        int r = ((n >> 3) - (m >> 3) + 7) * 15 + ((n & 7) - (m & 7) + 7);
        g_relbias[idx] = bias_table[r * 4 + h];
    }
}

__global__ void roundwts_kernel(const float* __restrict__ Wq,
                                const float* __restrict__ Wkv,
                                const float* __restrict__ Wo) {
    int idx = blockIdx.x * blockDim.x + threadIdx.x;
    if (idx < 16384)       g_wts[idx] = rnd32(Wq[idx]);
    else if (idx < 49152)  g_wts[idx] = rnd32(Wkv[idx - 16384]);
    else if (idx < 65536)  g_wts[idx] = rnd32(Wo[idx - 49152]);
}

using FragA  = wmma::fragment<wmma::matrix_a, 16, 16, 8, wmma::precision::tf32, wmma::row_major>;
using FragB  = wmma::fragment<wmma::matrix_b, 16, 16, 8, wmma::precision::tf32, wmma::col_major>;
using FragBR = wmma::fragment<wmma::matrix_b, 16, 16, 8, wmma::precision::tf32, wmma::row_major>;
using FragC  = wmma::fragment<wmma::accumulator, 16, 16, 8, float>;

// ======================= shared GEMM body: 64x128 tile = A(64x128) @ W^T =======================
// 256 threads, 8 warps. Warp w: col-tile w, row-tiles 0..3 (NT=4).
// A staged in smem (33.8KB -> 6 CTAs/SM); W fragments read directly from global (L2-hot).
__device__ __forceinline__ void gemm_body(const float* __restrict__ src, const float* __restrict__ Wg,
                                          const float* __restrict__ bias, float* __restrict__ dst,
                                          float scl, bool rin, bool rout) {
    __shared__ float sA[64 * 132];
    const int tid = threadIdx.x;
    const int w = tid >> 5;

    const float4* s4 = (const float4*)src;
    for (int i = tid; i < 2048; i += 256) {
        float4 v = s4[i];
        if (rin) { v.x = rnd32(v.x); v.y = rnd32(v.y); v.z = rnd32(v.z); v.w = rnd32(v.w); }
        int row = i >> 5, c4 = i & 31;
        *(float4*)(sA + row * 132 + c4 * 4) = v;
    }
    __syncthreads();

    FragC acc[4];
#pragma unroll
    for (int t = 0; t < 4; t++) wmma::fill_fragment(acc[t], 0.0f);

#pragma unroll
    for (int k = 0; k < 128; k += 8) {
        FragB b;
        wmma::load_matrix_sync(b, Wg + k + w * 16 * 128, 128);
#pragma unroll
        for (int t = 0; t < 4; t++) {
            FragA a;
            wmma::load_matrix_sync(a, sA + t * 16 * 132 + k, 132);
            wmma::mma_sync(acc[t], a, b, acc[t]);
        }
    }
    __syncthreads();

#pragma unroll
    for (int t = 0; t < 4; t++)
        wmma::store_matrix_sync(sA + t * 16 * 132 + w * 16, acc[t], 132, wmma::mem_row_major);
    __syncthreads();

    const float4* b4 = (const float4*)bias;
    float4* d4 = (float4*)dst;
    for (int i = tid; i < 2048; i += 256) {
        int row = i >> 5, c4 = i & 31;
        float4 v = *(const float4*)(sA + row * 132 + c4 * 4);
        float4 bb = b4[c4];
        if (rout) {
            v.x = rnd32((v.x + bb.x) * scl);
            v.y = rnd32((v.y + bb.y) * scl);
            v.z = rnd32((v.z + bb.z) * scl);
            v.w = rnd32((v.w + bb.w) * scl);
        } else {
            v.x += bb.x; v.y += bb.y; v.z += bb.z; v.w += bb.w;
        }
        d4[i] = v;
    }
}

// grid [0,8192): qh ; [8192,16384): k ; [16384,24576): v. Each CTA: 64 rows.
__global__ void __launch_bounds__(256)
proj_kernel(const float* __restrict__ q, const float* __restrict__ kv,
            const float* __restrict__ bq, const float* __restrict__ bkv) {
    const int cta = blockIdx.x;
    const int mtile = cta & 8191;
    const size_t off = (size_t)mtile * 8192;
    if (cta < 8192)
        gemm_body(q + off, g_wts, bq, g_qh + off, SCALE, true, true);
    else if (cta < 16384)
        gemm_body(kv + off, g_wts + 16384, bkv, g_k + off, 1.0f, true, true);
    else
        gemm_body(kv + off, g_wts + 32768, bkv + 128, g_v + off, 1.0f, true, true);
}

__global__ void __launch_bounds__(256)
outproj_kernel(const float* __restrict__ bo, float* __restrict__ out) {
    const size_t off = (size_t)blockIdx.x * 8192;
    gemm_body(g_x + off, g_wts + 49152, bo, out + off, 1.0f, false, false);
}

// ======================= attention core: CTA = (window, head), 128 threads =======================
__global__ void __launch_bounds__(128)
attn_kernel(const float* __restrict__ mask) {
    __shared__ float Ph[64 * 68];

    const int b = blockIdx.x >> 2;
    const int h = blockIdx.x & 3;
    const int tid = threadIdx.x;
    const int w = tid >> 5;
    const int lane = tid & 31;

    const float* qh = g_qh + (size_t)b * 8192 + h * 32;  // [64][128] slice, lda=128
    const float* kh = g_k + (size_t)b * 8192 + h * 32;
    const float* vh = g_v + (size_t)b * 8192 + h * 32;

    // S = qh_h @ k_h^T (K=32). Warp w: row-tile w, all 4 col-tiles.
    {
        FragC acc[4];
#pragma unroll
        for (int t = 0; t < 4; t++) wmma::fill_fragment(acc[t], 0.0f);
#pragma unroll
        for (int k = 0; k < 32; k += 8) {
            FragA a;
            wmma::load_matrix_sync(a, qh + w * 16 * 128 + k, 128);
#pragma unroll
            for (int t = 0; t < 4; t++) {
                FragB bf;
                wmma::load_matrix_sync(bf, kh + k + t * 16 * 128, 128);
                wmma::mma_sync(acc[t], a, bf, acc[t]);
            }
        }
#pragma unroll
        for (int t = 0; t < 4; t++)
            wmma::store_matrix_sync(Ph + w * 16 * 68 + t * 16, acc[t], 68, wmma::mem_row_major);
    }
    __syncthreads();

    // softmax: warp owns rows w*16..w*16+15 (qh pre-scaled); round P to tf32
    {
        const float* rb = g_relbias + h * 4096;
        const float* mk = mask + (size_t)(b & 4095) * 4096;
#pragma unroll
        for (int rr = 0; rr < 16; rr++) {
            int n = w * 16 + rr;
            float l0 = Ph[n * 68 + lane] + rb[n * 64 + lane] + mk[n * 64 + lane];
            float l1 = Ph[n * 68 + lane + 32] + rb[n * 64 + lane + 32] + mk[n * 64 + lane + 32];
            float mx = fmaxf(l0, l1);
#pragma unroll
            for (int o = 16; o; o >>= 1) mx = fmaxf(mx, __shfl_xor_sync(0xffffffffu, mx, o));
            float e0 = __expf(l0 - mx);
            float e1 = __expf(l1 - mx);
            float s = e0 + e1;
#pragma unroll
            for (int o = 16; o; o >>= 1) s += __shfl_xor_sync(0xffffffffu, s, o);
            float inv = 1.0f / s;
            Ph[n * 68 + lane] = rnd32(e0 * inv);
            Ph[n * 68 + lane + 32] = rnd32(e1 * inv);
        }
    }
    __syncthreads();

    // x_h = P @ v_h (K=64, B row-major), rounded -> g_x slice
    {
        float* xh = g_x + (size_t)b * 8192 + h * 32;
        FragC acc[2];
#pragma unroll
        for (int t = 0; t < 2; t++) wmma::fill_fragment(acc[t], 0.0f);
#pragma unroll
        for (int k = 0; k < 64; k += 8) {
            FragA a;
            wmma::load_matrix_sync(a, Ph + w * 16 * 68 + k, 68);
#pragma unroll
            for (int t = 0; t < 2; t++) {
                FragBR bf;
                wmma::load_matrix_sync(bf, vh + k * 128 + t * 16, 128);
                wmma::mma_sync(acc[t], a, bf, acc[t]);
            }
        }
#pragma unroll
        for (int t = 0; t < 2; t++) {
#pragma unroll
            for (int i = 0; i < acc[t].num_elements; i++) acc[t].x[i] = rnd32(acc[t].x[i]);
            wmma::store_matrix_sync(xh + w * 16 * 128 + t * 16, acc[t], 128, wmma::mem_row_major);
        }
    }
}

extern "C" void kernel_launch(void* const* d_in, const int* in_sizes, int n_in,
                              void* d_out, int out_size) {
    const float* q          = (const float*)d_in[0];
    const float* kv         = (const float*)d_in[1];
    const float* mask       = (const float*)d_in[2];
    const float* Wq         = (const float*)d_in[3];
    const float* bq         = (const float*)d_in[4];
    const float* Wkv        = (const float*)d_in[5];
    const float* bkv        = (const float*)d_in[6];
    const float* Wo         = (const float*)d_in[7];
    const float* bo         = (const float*)d_in[8];
    const float* bias_table = (const float*)d_in[9];
    float* out = (float*)d_out;

    relbias_kernel<<<64, 256>>>(bias_table);
    roundwts_kernel<<<256, 256>>>(Wq, Wkv, Wo);
    proj_kernel<<<24576, 256>>>(q, kv, bq, bkv);
    attn_kernel<<<32768, 128>>>(mask);
    outproj_kernel<<<8192, 256>>>(bo, out);
}

// round 9
// speedup vs baseline: 1.5909x; 1.5909x over previous
#include <cuda_runtime.h>
#include <mma.h>
#include <cstdint>

using namespace nvcuda;

#define SCALE 0.17677669529663687f  // 1/sqrt(32)

__device__ float g_relbias[4 * 64 * 64];
__device__ float g_wts[65536];   // tf32-rounded [SCALE*Wq | Wk | Wv | Wo]
__device__ float g_qh[67108864]; // [524288][128] q-proj (scale folded), rounded
__device__ float g_k [67108864];
__device__ float g_v [67108864];
__device__ float g_x [67108864]; // attn output, tf32-rounded

__device__ __forceinline__ float rnd32(float x) {
    float r;
    asm("cvt.rna.tf32.f32 %0, %1;" : "=f"(r) : "f"(x));
    return r;
}

__global__ void relbias_kernel(const float* __restrict__ bias_table) {
    int idx = blockIdx.x * blockDim.x + threadIdx.x;
    if (idx < 4 * 64 * 64) {
        int h = idx >> 12;
        int n = (idx >> 6) & 63;
        int m = idx & 63;
        int r = ((n >> 3) - (m >> 3) + 7) * 15 + ((n & 7) - (m & 7) + 7);
        g_relbias[idx] = bias_table[r * 4 + h];
    }
}

// Wq gets SCALE folded in (so q-proj output is pre-scaled)
__global__ void roundwts_kernel(const float* __restrict__ Wq,
                                const float* __restrict__ Wkv,
                                const float* __restrict__ Wo) {
    int idx = blockIdx.x * blockDim.x + threadIdx.x;
    if (idx < 16384)       g_wts[idx] = rnd32(Wq[idx] * SCALE);
    else if (idx < 49152)  g_wts[idx] = rnd32(Wkv[idx - 16384]);
    else if (idx < 65536)  g_wts[idx] = rnd32(Wo[idx - 49152]);
}

using FragA  = wmma::fragment<wmma::matrix_a, 16, 16, 8, wmma::precision::tf32, wmma::row_major>;
using FragB  = wmma::fragment<wmma::matrix_b, 16, 16, 8, wmma::precision::tf32, wmma::col_major>;
using FragBR = wmma::fragment<wmma::matrix_b, 16, 16, 8, wmma::precision::tf32, wmma::row_major>;
using FragC  = wmma::fragment<wmma::accumulator, 16, 16, 8, float>;

// ================== GEMM: C[rows,128] = A[rows,128] @ W^T, B fragments in registers ==================
// 256 thr / 8 warps; warp w owns col-tile w. All 16 k-step B fragments preloaded to registers
// (amortized over 8 row-tiles of 32 rows). Bias enters as C-init from replicated smem tile.
__global__ void __launch_bounds__(256, 2)
mm2_kernel(const float* __restrict__ q, const float* __restrict__ kv,
           const float* __restrict__ bq, const float* __restrict__ bkv,
           const float* __restrict__ bo, float* __restrict__ out, int mode) {
    __shared__ float sA[2][32 * 132];
    __shared__ float sBias[16 * 132];

    const int tid = threadIdx.x;
    const int w = tid >> 5;

    const float* src; const float* Wg; const float* bias; float* dst;
    float scl; bool rin, rout; size_t row0;
    if (mode == 0) {
        int m = blockIdx.x % 3;          // interleave q/k/v over same rows -> kv L2 reuse
        size_t chunk = blockIdx.x / 3;
        row0 = chunk * 256;
        if (m == 0)      { src = q;  Wg = g_wts;         bias = bq;        dst = g_qh; scl = SCALE; }
        else if (m == 1) { src = kv; Wg = g_wts + 16384; bias = bkv;       dst = g_k;  scl = 1.0f; }
        else             { src = kv; Wg = g_wts + 32768; bias = bkv + 128; dst = g_v;  scl = 1.0f; }
        rin = true; rout = true;
    } else {
        row0 = (size_t)blockIdx.x * 256;
        src = g_x; Wg = g_wts + 49152; bias = bo; dst = out; scl = 1.0f;
        rin = false; rout = false;
    }

    // replicated bias tile (16 identical rows)
    for (int i = tid; i < 2048; i += 256) {
        int r = i >> 7, c = i & 127;
        sBias[r * 132 + c] = bias[c] * scl;
    }

    // preload all B fragments for this warp's col strip (64 regs)
    FragB bfr[16];
#pragma unroll
    for (int kk = 0; kk < 16; kk++)
        wmma::load_matrix_sync(bfr[kk], Wg + kk * 8 + w * 16 * 128, 128);

    // prefetch tile 0 into registers, stage to buffer 0
    float4 pf[4];
    {
        const float4* s4 = (const float4*)(src + row0 * 128);
#pragma unroll
        for (int u = 0; u < 4; u++) pf[u] = s4[tid + 256 * u];
#pragma unroll
        for (int u = 0; u < 4; u++) {
            int i = tid + 256 * u;
            int r = i >> 5, c4 = i & 31;
            float4 v = pf[u];
            if (rin) { v.x = rnd32(v.x); v.y = rnd32(v.y); v.z = rnd32(v.z); v.w = rnd32(v.w); }
            *(float4*)(sA[0] + r * 132 + c4 * 4) = v;
        }
    }
    __syncthreads();

    for (int j = 0; j < 8; j++) {
        // issue prefetch LDGs for next tile (hidden under compute)
        if (j < 7) {
            const float4* n4 = (const float4*)(src + (row0 + (size_t)(j + 1) * 32) * 128);
#pragma unroll
            for (int u = 0; u < 4; u++) pf[u] = n4[tid + 256 * u];
        }

        const float* buf = sA[j & 1];
        FragC c0, c1;
        wmma::load_matrix_sync(c0, sBias + w * 16, 132, wmma::mem_row_major);
        wmma::load_matrix_sync(c1, sBias + w * 16, 132, wmma::mem_row_major);
#pragma unroll
        for (int kk = 0; kk < 16; kk++) {
            FragA a0, a1;
            wmma::load_matrix_sync(a0, buf + kk * 8, 132);
            wmma::load_matrix_sync(a1, buf + 16 * 132 + kk * 8, 132);
            wmma::mma_sync(c0, a0, bfr[kk], c0);
            wmma::mma_sync(c1, a1, bfr[kk], c1);
        }
        if (rout) {
#pragma unroll
            for (int i = 0; i < c0.num_elements; i++) c0.x[i] = rnd32(c0.x[i]);
#pragma unroll
            for (int i = 0; i < c1.num_elements; i++) c1.x[i] = rnd32(c1.x[i]);
        }
        const size_t rb = row0 + (size_t)j * 32;
        wmma::store_matrix_sync(dst + rb * 128 + w * 16, c0, 128, wmma::mem_row_major);
        wmma::store_matrix_sync(dst + (rb + 16) * 128 + w * 16, c1, 128, wmma::mem_row_major);

        // stage next tile into the other buffer (free since end of iter j-1)
        if (j < 7) {
            float* nb = sA[(j + 1) & 1];
#pragma unroll
            for (int u = 0; u < 4; u++) {
                int i = tid + 256 * u;
                int r = i >> 5, c4 = i & 31;
                float4 v = pf[u];
                if (rin) { v.x = rnd32(v.x); v.y = rnd32(v.y); v.z = rnd32(v.z); v.w = rnd32(v.w); }
                *(float4*)(nb + r * 132 + c4 * 4) = v;
            }
        }
        __syncthreads();
    }
}

// ===================== attention core (wmma, smem-staged head slices) =====================
__global__ void __launch_bounds__(128)
attn_kernel(const float* __restrict__ mask) {
    __shared__ float sQ[64 * 36], sK[64 * 36], sV[64 * 36], Ph[64 * 68];

    const int b = blockIdx.x >> 2;
    const int h = blockIdx.x & 3;
    const int tid = threadIdx.x;
    const int w = tid >> 5;
    const int lane = tid & 31;

    // coalesced staging of 64x32 head slices
    const float* qs = g_qh + (size_t)b * 8192 + h * 32;
    const float* ks = g_k + (size_t)b * 8192 + h * 32;
    const float* vs = g_v + (size_t)b * 8192 + h * 32;
    for (int i = tid; i < 512; i += 128) {
        int r = i >> 3, c4 = i & 7;
        *(float4*)(sQ + r * 36 + c4 * 4) = *(const float4*)(qs + r * 128 + c4 * 4);
        *(float4*)(sK + r * 36 + c4 * 4) = *(const float4*)(ks + r * 128 + c4 * 4);
        *(float4*)(sV + r * 36 + c4 * 4) = *(const float4*)(vs + r * 128 + c4 * 4);
    }
    __syncthreads();

    // S = qh @ k^T (K=32): warp w -> row-tile w, 4 col-tiles
    {
        FragC acc[4];
#pragma unroll
        for (int t = 0; t < 4; t++) wmma::fill_fragment(acc[t], 0.0f);
#pragma unroll
        for (int k = 0; k < 32; k += 8) {
            FragA a;
            wmma::load_matrix_sync(a, sQ + w * 16 * 36 + k, 36);
#pragma unroll
            for (int t = 0; t < 4; t++) {
                FragB bf;
                wmma::load_matrix_sync(bf, sK + k + t * 16 * 36, 36);
                wmma::mma_sync(acc[t], a, bf, acc[t]);
            }
        }
#pragma unroll
        for (int t = 0; t < 4; t++)
            wmma::store_matrix_sync(Ph + w * 16 * 68 + t * 16, acc[t], 68, wmma::mem_row_major);
    }
    __syncthreads();

    // softmax (qh pre-scaled); round P to tf32
    {
        const float* rb = g_relbias + h * 4096;
        const float* mk = mask + (size_t)(b & 4095) * 4096;
#pragma unroll
        for (int rr = 0; rr < 16; rr++) {
            int n = w * 16 + rr;
            float l0 = Ph[n * 68 + lane] + rb[n * 64 + lane] + mk[n * 64 + lane];
            float l1 = Ph[n * 68 + lane + 32] + rb[n * 64 + lane + 32] + mk[n * 64 + lane + 32];
            float mx = fmaxf(l0, l1);
#pragma unroll
            for (int o = 16; o; o >>= 1) mx = fmaxf(mx, __shfl_xor_sync(0xffffffffu, mx, o));
            float e0 = __expf(l0 - mx);
            float e1 = __expf(l1 - mx);
            float s = e0 + e1;
#pragma unroll
            for (int o = 16; o; o >>= 1) s += __shfl_xor_sync(0xffffffffu, s, o);
            float inv = 1.0f / s;
            Ph[n * 68 + lane] = rnd32(e0 * inv);
            Ph[n * 68 + lane + 32] = rnd32(e1 * inv);
        }
    }
    __syncthreads();

    // x = P @ v (K=64, B row-major), rounded -> stage into sQ, then coalesced write
    {
        FragC acc[2];
#pragma unroll
        for (int t = 0; t < 2; t++) wmma::fill_fragment(acc[t], 0.0f);
#pragma unroll
        for (int k = 0; k < 64; k += 8) {
            FragA a;
            wmma::load_matrix_sync(a, Ph + w * 16 * 68 + k, 68);
#pragma unroll
            for (int t = 0; t < 2; t++) {
                FragBR bf;
                wmma::load_matrix_sync(bf, sV + k * 36 + t * 16, 36);
                wmma::mma_sync(acc[t], a, bf, acc[t]);
            }
        }
        __syncthreads();   // all warps done reading sQ region? (sQ reused below)
#pragma unroll
        for (int t = 0; t < 2; t++) {
#pragma unroll
            for (int i = 0; i < acc[t].num_elements; i++) acc[t].x[i] = rnd32(acc[t].x[i]);
            wmma::store_matrix_sync(sQ + w * 16 * 36 + t * 16, acc[t], 36, wmma::mem_row_major);
        }
    }
    __syncthreads();

    float* xd = g_x + (size_t)b * 8192 + h * 32;
    for (int i = tid; i < 512; i += 128) {
        int r = i >> 3, c4 = i & 7;
        *(float4*)(xd + r * 128 + c4 * 4) = *(const float4*)(sQ + r * 36 + c4 * 4);
    }
}

extern "C" void kernel_launch(void* const* d_in, const int* in_sizes, int n_in,
                              void* d_out, int out_size) {
    const float* q          = (const float*)d_in[0];
    const float* kv         = (const float*)d_in[1];
    const float* mask       = (const float*)d_in[2];
    const float* Wq         = (const float*)d_in[3];
    const float* bq         = (const float*)d_in[4];
    const float* Wkv        = (const float*)d_in[5];
    const float* bkv        = (const float*)d_in[6];
    const float* Wo         = (const float*)d_in[7];
    const float* bo         = (const float*)d_in[8];
    const float* bias_table = (const float*)d_in[9];
    float* out = (float*)d_out;

    relbias_kernel<<<64, 256>>>(bias_table);
    roundwts_kernel<<<256, 256>>>(Wq, Wkv, Wo);

    mm2_kernel<<<6144, 256>>>(q, kv, bq, bkv, bo, out, 0);   // qh, k, v projections
    attn_kernel<<<32768, 128>>>(mask);
    mm2_kernel<<<2048, 256>>>(q, kv, bq, bkv, bo, out, 1);   // out-proj
}

// round 10
// speedup vs baseline: 1.7604x; 1.1065x over previous
#include <cuda_runtime.h>
#include <mma.h>
#include <cstdint>

using namespace nvcuda;

#define SCALE 0.17677669529663687f  // 1/sqrt(32)

__device__ float g_relbias[4 * 64 * 64];
__device__ float g_wts[65536];   // tf32-rounded [SCALE*Wq | Wk | Wv | Wo]
__device__ float g_qh[67108864]; // [524288][128] q-proj (scale folded), rounded
__device__ float g_k [67108864];
__device__ float g_v [67108864];
__device__ float g_x [67108864]; // attn output, tf32-rounded

__device__ __forceinline__ float rnd32(float x) {
    float r;
    asm("cvt.rna.tf32.f32 %0, %1;" : "=f"(r) : "f"(x));
    return r;
}

__global__ void relbias_kernel(const float* __restrict__ bias_table) {
    int idx = blockIdx.x * blockDim.x + threadIdx.x;
    if (idx < 4 * 64 * 64) {
        int h = idx >> 12;
        int n = (idx >> 6) & 63;
        int m = idx & 63;
        int r = ((n >> 3) - (m >> 3) + 7) * 15 + ((n & 7) - (m & 7) + 7);
        g_relbias[idx] = bias_table[r * 4 + h];
    }
}

// Wq gets SCALE folded in (so q-proj output is pre-scaled)
__global__ void roundwts_kernel(const float* __restrict__ Wq,
                                const float* __restrict__ Wkv,
                                const float* __restrict__ Wo) {
    int idx = blockIdx.x * blockDim.x + threadIdx.x;
    if (idx < 16384)       g_wts[idx] = rnd32(Wq[idx] * SCALE);
    else if (idx < 49152)  g_wts[idx] = rnd32(Wkv[idx - 16384]);
    else if (idx < 65536)  g_wts[idx] = rnd32(Wo[idx - 49152]);
}

using FragA  = wmma::fragment<wmma::matrix_a, 16, 16, 8, wmma::precision::tf32, wmma::row_major>;
using FragB  = wmma::fragment<wmma::matrix_b, 16, 16, 8, wmma::precision::tf32, wmma::col_major>;
using FragBR = wmma::fragment<wmma::matrix_b, 16, 16, 8, wmma::precision::tf32, wmma::row_major>;
using FragC  = wmma::fragment<wmma::accumulator, 16, 16, 8, float>;

// ================== GEMM: C[rows,128] = A[rows,128] @ W^T, B fragments in registers ==================
__global__ void __launch_bounds__(256, 2)
mm2_kernel(const float* __restrict__ q, const float* __restrict__ kv,
           const float* __restrict__ bq, const float* __restrict__ bkv,
           const float* __restrict__ bo, float* __restrict__ out, int mode) {
    __shared__ float sA[2][32 * 132];
    __shared__ float sBias[16 * 132];

    const int tid = threadIdx.x;
    const int w = tid >> 5;

    const float* src; const float* Wg; const float* bias; float* dst;
    float scl; bool rin, rout; size_t row0;
    if (mode == 0) {
        int m = blockIdx.x % 3;          // interleave q/k/v over same rows -> kv L2 reuse
        size_t chunk = blockIdx.x / 3;
        row0 = chunk * 256;
        if (m == 0)      { src = q;  Wg = g_wts;         bias = bq;        dst = g_qh; scl = SCALE; }
        else if (m == 1) { src = kv; Wg = g_wts + 16384; bias = bkv;       dst = g_k;  scl = 1.0f; }
        else             { src = kv; Wg = g_wts + 32768; bias = bkv + 128; dst = g_v;  scl = 1.0f; }
        rin = true; rout = true;
    } else {
        row0 = (size_t)blockIdx.x * 256;
        src = g_x; Wg = g_wts + 49152; bias = bo; dst = out; scl = 1.0f;
        rin = false; rout = false;
    }

    // replicated bias tile (16 identical rows)
    for (int i = tid; i < 2048; i += 256) {
        int r = i >> 7, c = i & 127;
        sBias[r * 132 + c] = bias[c] * scl;
    }

    // preload all B fragments for this warp's col strip (64 regs)
    FragB bfr[16];
#pragma unroll
    for (int kk = 0; kk < 16; kk++)
        wmma::load_matrix_sync(bfr[kk], Wg + kk * 8 + w * 16 * 128, 128);

    // prefetch tile 0 into registers, stage to buffer 0
    float4 pf[4];
    {
        const float4* s4 = (const float4*)(src + row0 * 128);
#pragma unroll
        for (int u = 0; u < 4; u++) pf[u] = s4[tid + 256 * u];
#pragma unroll
        for (int u = 0; u < 4; u++) {
            int i = tid + 256 * u;
            int r = i >> 5, c4 = i & 31;
            float4 v = pf[u];
            if (rin) { v.x = rnd32(v.x); v.y = rnd32(v.y); v.z = rnd32(v.z); v.w = rnd32(v.w); }
            *(float4*)(sA[0] + r * 132 + c4 * 4) = v;
        }
    }
    __syncthreads();

    for (int j = 0; j < 8; j++) {
        if (j < 7) {
            const float4* n4 = (const float4*)(src + (row0 + (size_t)(j + 1) * 32) * 128);
#pragma unroll
            for (int u = 0; u < 4; u++) pf[u] = n4[tid + 256 * u];
        }

        const float* buf = sA[j & 1];
        FragC c0, c1;
        wmma::load_matrix_sync(c0, sBias + w * 16, 132, wmma::mem_row_major);
        wmma::load_matrix_sync(c1, sBias + w * 16, 132, wmma::mem_row_major);
#pragma unroll
        for (int kk = 0; kk < 16; kk++) {
            FragA a0, a1;
            wmma::load_matrix_sync(a0, buf + kk * 8, 132);
            wmma::load_matrix_sync(a1, buf + 16 * 132 + kk * 8, 132);
            wmma::mma_sync(c0, a0, bfr[kk], c0);
            wmma::mma_sync(c1, a1, bfr[kk], c1);
        }
        if (rout) {
#pragma unroll
            for (int i = 0; i < c0.num_elements; i++) c0.x[i] = rnd32(c0.x[i]);
#pragma unroll
            for (int i = 0; i < c1.num_elements; i++) c1.x[i] = rnd32(c1.x[i]);
        }
        const size_t rb = row0 + (size_t)j * 32;
        wmma::store_matrix_sync(dst + rb * 128 + w * 16, c0, 128, wmma::mem_row_major);
        wmma::store_matrix_sync(dst + (rb + 16) * 128 + w * 16, c1, 128, wmma::mem_row_major);

        if (j < 7) {
            float* nb = sA[(j + 1) & 1];
#pragma unroll
            for (int u = 0; u < 4; u++) {
                int i = tid + 256 * u;
                int r = i >> 5, c4 = i & 31;
                float4 v = pf[u];
                if (rin) { v.x = rnd32(v.x); v.y = rnd32(v.y); v.z = rnd32(v.z); v.w = rnd32(v.w); }
                *(float4*)(nb + r * 132 + c4 * 4) = v;
            }
        }
        __syncthreads();
    }
}

// ===================== attention core: overlapped smem (27KB), 8 CTAs/SM =====================
// Region A [4608 floats]: sQ(64x36)@0 + sK(64x36)@2304 during S-GEMM; then Ph(64x68)@0;
// then x-staging(64x36)@0. sV(64x36) separate.
__global__ void __launch_bounds__(128, 8)
attn_kernel(const float* __restrict__ mask) {
    __shared__ float smA[4608];
    __shared__ float sV[2304];
    float* sQ = smA;
    float* sK = smA + 2304;
    float* Ph = smA;

    const int b = blockIdx.x >> 2;
    const int h = blockIdx.x & 3;
    const int tid = threadIdx.x;
    const int w = tid >> 5;
    const int lane = tid & 31;

    // coalesced staging of 64x32 head slices
    const float* qs = g_qh + (size_t)b * 8192 + h * 32;
    const float* ks = g_k + (size_t)b * 8192 + h * 32;
    const float* vs = g_v + (size_t)b * 8192 + h * 32;
    for (int i = tid; i < 512; i += 128) {
        int r = i >> 3, c4 = i & 7;
        *(float4*)(sQ + r * 36 + c4 * 4) = *(const float4*)(qs + r * 128 + c4 * 4);
        *(float4*)(sK + r * 36 + c4 * 4) = *(const float4*)(ks + r * 128 + c4 * 4);
        *(float4*)(sV + r * 36 + c4 * 4) = *(const float4*)(vs + r * 128 + c4 * 4);
    }
    __syncthreads();

    // S = qh @ k^T (K=32): warp w -> row-tile w, 4 col-tiles; acc stays in regs across barrier
    FragC acc[4];
#pragma unroll
    for (int t = 0; t < 4; t++) wmma::fill_fragment(acc[t], 0.0f);
#pragma unroll
    for (int k = 0; k < 32; k += 8) {
        FragA a;
        wmma::load_matrix_sync(a, sQ + w * 16 * 36 + k, 36);
#pragma unroll
        for (int t = 0; t < 4; t++) {
            FragB bf;
            wmma::load_matrix_sync(bf, sK + k + t * 16 * 36, 36);
            wmma::mma_sync(acc[t], a, bf, acc[t]);
        }
    }
    __syncthreads();   // all warps done READING sQ/sK -> safe to overlay Ph

#pragma unroll
    for (int t = 0; t < 4; t++)
        wmma::store_matrix_sync(Ph + w * 16 * 68 + t * 16, acc[t], 68, wmma::mem_row_major);
    __syncthreads();

    // softmax (qh pre-scaled); round P to tf32
    {
        const float* rb = g_relbias + h * 4096;
        const float* mk = mask + (size_t)(b & 4095) * 4096;
#pragma unroll
        for (int rr = 0; rr < 16; rr++) {
            int n = w * 16 + rr;
            float l0 = Ph[n * 68 + lane] + rb[n * 64 + lane] + mk[n * 64 + lane];
            float l1 = Ph[n * 68 + lane + 32] + rb[n * 64 + lane + 32] + mk[n * 64 + lane + 32];
            float mx = fmaxf(l0, l1);
#pragma unroll
            for (int o = 16; o; o >>= 1) mx = fmaxf(mx, __shfl_xor_sync(0xffffffffu, mx, o));
            float e0 = __expf(l0 - mx);
            float e1 = __expf(l1 - mx);
            float s = e0 + e1;
#pragma unroll
            for (int o = 16; o; o >>= 1) s += __shfl_xor_sync(0xffffffffu, s, o);
            float inv = 1.0f / s;
            Ph[n * 68 + lane] = rnd32(e0 * inv);
            Ph[n * 68 + lane + 32] = rnd32(e1 * inv);
        }
    }
    __syncthreads();

    // x = P @ v (K=64, B row-major), rounded; acc in regs across barrier
    FragC xc[2];
#pragma unroll
    for (int t = 0; t < 2; t++) wmma::fill_fragment(xc[t], 0.0f);
#pragma unroll
    for (int k = 0; k < 64; k += 8) {
        FragA a;
        wmma::load_matrix_sync(a, Ph + w * 16 * 68 + k, 68);
#pragma unroll
        for (int t = 0; t < 2; t++) {
            FragBR bf;
            wmma::load_matrix_sync(bf, sV + k * 36 + t * 16, 36);
            wmma::mma_sync(xc[t], a, bf, xc[t]);
        }
    }
    __syncthreads();   // all warps done READING Ph -> safe to overlay x staging

#pragma unroll
    for (int t = 0; t < 2; t++) {
#pragma unroll
        for (int i = 0; i < xc[t].num_elements; i++) xc[t].x[i] = rnd32(xc[t].x[i]);
        wmma::store_matrix_sync(smA + w * 16 * 36 + t * 16, xc[t], 36, wmma::mem_row_major);
    }
    __syncthreads();

    float* xd = g_x + (size_t)b * 8192 + h * 32;
    for (int i = tid; i < 512; i += 128) {
        int r = i >> 3, c4 = i & 7;
        *(float4*)(xd + r * 128 + c4 * 4) = *(const float4*)(smA + r * 36 + c4 * 4);
    }
}

extern "C" void kernel_launch(void* const* d_in, const int* in_sizes, int n_in,
                              void* d_out, int out_size) {
    const float* q          = (const float*)d_in[0];
    const float* kv         = (const float*)d_in[1];
    const float* mask       = (const float*)d_in[2];
    const float* Wq         = (const float*)d_in[3];
    const float* bq         = (const float*)d_in[4];
    const float* Wkv        = (const float*)d_in[5];
    const float* bkv        = (const float*)d_in[6];
    const float* Wo         = (const float*)d_in[7];
    const float* bo         = (const float*)d_in[8];
    const float* bias_table = (const float*)d_in[9];
    float* out = (float*)d_out;

    relbias_kernel<<<64, 256>>>(bias_table);
    roundwts_kernel<<<256, 256>>>(Wq, Wkv, Wo);

    mm2_kernel<<<6144, 256>>>(q, kv, bq, bkv, bo, out, 0);   // qh, k, v projections
    attn_kernel<<<32768, 128>>>(mask);
    mm2_kernel<<<2048, 256>>>(q, kv, bq, bkv, bo, out, 1);   // out-proj
}

// round 11
// speedup vs baseline: 1.9850x; 1.1276x over previous
#include <cuda_runtime.h>
#include <mma.h>
#include <cstdint>

using namespace nvcuda;

#define SCALE 0.17677669529663687f  // 1/sqrt(32)

__device__ float g_relbias[4 * 64 * 64];
__device__ float g_wts[65536];   // tf32-rounded [SCALE*Wq | Wk | Wv | Wo]
__device__ float g_qh[67108864]; // [524288][128] q-proj (scale folded), rounded
__device__ float g_k [67108864];
__device__ float g_v [67108864];
__device__ float g_x [67108864]; // attn output, tf32-rounded

__device__ __forceinline__ float rnd32(float x) {
    float r;
    asm("cvt.rna.tf32.f32 %0, %1;" : "=f"(r) : "f"(x));
    return r;
}

__global__ void relbias_kernel(const float* __restrict__ bias_table) {
    int idx = blockIdx.x * blockDim.x + threadIdx.x;
    if (idx < 4 * 64 * 64) {
        int h = idx >> 12;
        int n = (idx >> 6) & 63;
        int m = idx & 63;
        int r = ((n >> 3) - (m >> 3) + 7) * 15 + ((n & 7) - (m & 7) + 7);
        g_relbias[idx] = bias_table[r * 4 + h];
    }
}

// Wq gets SCALE folded in (so q-proj output is pre-scaled)
__global__ void roundwts_kernel(const float* __restrict__ Wq,
                                const float* __restrict__ Wkv,
                                const float* __restrict__ Wo) {
    int idx = blockIdx.x * blockDim.x + threadIdx.x;
    if (idx < 16384)       g_wts[idx] = rnd32(Wq[idx] * SCALE);
    else if (idx < 49152)  g_wts[idx] = rnd32(Wkv[idx - 16384]);
    else if (idx < 65536)  g_wts[idx] = rnd32(Wo[idx - 49152]);
}

// raw tf32 mma: D(m16n8) += A(m16k8) * B(k8n8)
__device__ __forceinline__ void mma168(float& c0, float& c1, float& c2, float& c3,
                                       uint32_t a0, uint32_t a1, uint32_t a2, uint32_t a3,
                                       uint32_t b0, uint32_t b1) {
    asm volatile(
        "mma.sync.aligned.m16n8k8.row.col.f32.tf32.tf32.f32 "
        "{%0,%1,%2,%3}, {%4,%5,%6,%7}, {%8,%9}, {%0,%1,%2,%3};"
        : "+f"(c0), "+f"(c1), "+f"(c2), "+f"(c3)
        : "r"(a0), "r"(a1), "r"(a2), "r"(a3), "r"(b0), "r"(b1));
}

// ============= GEMM: C[128 rows,128] = A @ W^T  (512 thr, 16 warps x n8 strip) =============
// B frags (32 regs) preloaded from L2-hot g_wts; A staged 32 rows/iter, double-buffered;
// C in regs, bias in regs, direct float2 STG. 2 CTAs/SM -> 32 warps.
__global__ void __launch_bounds__(512, 2)
mm3_kernel(const float* __restrict__ q, const float* __restrict__ kv,
           const float* __restrict__ bq, const float* __restrict__ bkv,
           const float* __restrict__ bo, float* __restrict__ out, int mode) {
    __shared__ float sA[2][32 * 132];

    const int tid = threadIdx.x;
    const int w = tid >> 5;
    const int lane = tid & 31;
    const int g = lane >> 2;
    const int tig = lane & 3;
    const int n0 = w * 8;
    const int cc = n0 + 2 * tig;     // this thread's output column pair

    const float* src; const float* Wg; const float* bias; float* dst;
    float scl; bool rin, rout; size_t row0;
    if (mode == 0) {
        int m = blockIdx.x % 3;          // interleave q/k/v -> kv L2 reuse
        size_t chunk = blockIdx.x / 3;
        row0 = chunk * 128;
        if (m == 0)      { src = q;  Wg = g_wts;         bias = bq;        dst = g_qh; scl = SCALE; }
        else if (m == 1) { src = kv; Wg = g_wts + 16384; bias = bkv;       dst = g_k;  scl = 1.0f; }
        else             { src = kv; Wg = g_wts + 32768; bias = bkv + 128; dst = g_v;  scl = 1.0f; }
        rin = true; rout = true;
    } else {
        row0 = (size_t)blockIdx.x * 128;
        src = g_x; Wg = g_wts + 49152; bias = bo; dst = out; scl = 1.0f;
        rin = false; rout = false;
    }

    const float bias0 = bias[cc] * scl;
    const float bias1 = bias[cc + 1] * scl;

    // preload B fragments: b0=(k=tig, n=n0+g), b1=(k=tig+4, n=n0+g); W row-major [n][k]
    uint32_t B[16][2];
#pragma unroll
    for (int kk = 0; kk < 16; kk++) {
        B[kk][0] = __float_as_uint(Wg[(n0 + g) * 128 + kk * 8 + tig]);
        B[kk][1] = __float_as_uint(Wg[(n0 + g) * 128 + kk * 8 + tig + 4]);
    }

    // stage tile 0 (32 rows): 1024 float4 / 512 thr = 2 each
    {
        const float4* s4 = (const float4*)(src + row0 * 128);
#pragma unroll
        for (int u = 0; u < 2; u++) {
            int i = tid + 512 * u;
            float4 v = s4[i];
            if (rin) { v.x = rnd32(v.x); v.y = rnd32(v.y); v.z = rnd32(v.z); v.w = rnd32(v.w); }
            *(float4*)(sA[0] + (i >> 5) * 132 + (i & 31) * 4) = v;
        }
    }
    __syncthreads();

    for (int j = 0; j < 4; j++) {
        float4 pf0, pf1;
        if (j < 3) {
            const float4* n4 = (const float4*)(src + (row0 + (size_t)(j + 1) * 32) * 128);
            pf0 = n4[tid];
            pf1 = n4[tid + 512];
        }

        const float* buf = sA[j & 1];
        float c00 = bias0, c01 = bias1, c02 = bias0, c03 = bias1;  // rows g, g+8
        float c10 = bias0, c11 = bias1, c12 = bias0, c13 = bias1;  // rows 16+g, 16+g+8
#pragma unroll
        for (int kk = 0; kk < 16; kk++) {
            const float* bk = buf + kk * 8 + tig;
            uint32_t a0 = __float_as_uint(bk[g * 132]);
            uint32_t a1 = __float_as_uint(bk[(g + 8) * 132]);
            uint32_t a2 = __float_as_uint(bk[g * 132 + 4]);
            uint32_t a3 = __float_as_uint(bk[(g + 8) * 132 + 4]);
            mma168(c00, c01, c02, c03, a0, a1, a2, a3, B[kk][0], B[kk][1]);
            uint32_t a4 = __float_as_uint(bk[(16 + g) * 132]);
            uint32_t a5 = __float_as_uint(bk[(24 + g) * 132]);
            uint32_t a6 = __float_as_uint(bk[(16 + g) * 132 + 4]);
            uint32_t a7 = __float_as_uint(bk[(24 + g) * 132 + 4]);
            mma168(c10, c11, c12, c13, a4, a5, a6, a7, B[kk][0], B[kk][1]);
        }

        if (rout) {
            c00 = rnd32(c00); c01 = rnd32(c01); c02 = rnd32(c02); c03 = rnd32(c03);
            c10 = rnd32(c10); c11 = rnd32(c11); c12 = rnd32(c12); c13 = rnd32(c13);
        }
        const size_t rb = row0 + (size_t)j * 32;
        *(float2*)(dst + (rb + g) * 128 + cc)      = make_float2(c00, c01);
        *(float2*)(dst + (rb + g + 8) * 128 + cc)  = make_float2(c02, c03);
        *(float2*)(dst + (rb + 16 + g) * 128 + cc) = make_float2(c10, c11);
        *(float2*)(dst + (rb + 24 + g) * 128 + cc) = make_float2(c12, c13);

        if (j < 3) {
            float* nb = sA[(j + 1) & 1];
#pragma unroll
            for (int u = 0; u < 2; u++) {
                int i = tid + 512 * u;
                float4 v = (u == 0) ? pf0 : pf1;
                if (rin) { v.x = rnd32(v.x); v.y = rnd32(v.y); v.z = rnd32(v.z); v.w = rnd32(v.w); }
                *(float4*)(nb + (i >> 5) * 132 + (i & 31) * 4) = v;
            }
        }
        __syncthreads();
    }
}

// ===================== attention core: overlapped smem (27KB), 8 CTAs/SM =====================
using FragA  = wmma::fragment<wmma::matrix_a, 16, 16, 8, wmma::precision::tf32, wmma::row_major>;
using FragB  = wmma::fragment<wmma::matrix_b, 16, 16, 8, wmma::precision::tf32, wmma::col_major>;
using FragBR = wmma::fragment<wmma::matrix_b, 16, 16, 8, wmma::precision::tf32, wmma::row_major>;
using FragC  = wmma::fragment<wmma::accumulator, 16, 16, 8, float>;

__global__ void __launch_bounds__(128, 8)
attn_kernel(const float* __restrict__ mask) {
    __shared__ float smA[4608];
    __shared__ float sV[2304];
    float* sQ = smA;
    float* sK = smA + 2304;
    float* Ph = smA;

    const int b = blockIdx.x >> 2;
    const int h = blockIdx.x & 3;
    const int tid = threadIdx.x;
    const int w = tid >> 5;
    const int lane = tid & 31;

    const float* qs = g_qh + (size_t)b * 8192 + h * 32;
    const float* ks = g_k + (size_t)b * 8192 + h * 32;
    const float* vs = g_v + (size_t)b * 8192 + h * 32;
    for (int i = tid; i < 512; i += 128) {
        int r = i >> 3, c4 = i & 7;
        *(float4*)(sQ + r * 36 + c4 * 4) = *(const float4*)(qs + r * 128 + c4 * 4);
        *(float4*)(sK + r * 36 + c4 * 4) = *(const float4*)(ks + r * 128 + c4 * 4);
        *(float4*)(sV + r * 36 + c4 * 4) = *(const float4*)(vs + r * 128 + c4 * 4);
    }
    __syncthreads();

    FragC acc[4];
#pragma unroll
    for (int t = 0; t < 4; t++) wmma::fill_fragment(acc[t], 0.0f);
#pragma unroll
    for (int k = 0; k < 32; k += 8) {
        FragA a;
        wmma::load_matrix_sync(a, sQ + w * 16 * 36 + k, 36);
#pragma unroll
        for (int t = 0; t < 4; t++) {
            FragB bf;
            wmma::load_matrix_sync(bf, sK + k + t * 16 * 36, 36);
            wmma::mma_sync(acc[t], a, bf, acc[t]);
        }
    }
    __syncthreads();   // done READING sQ/sK -> overlay Ph

#pragma unroll
    for (int t = 0; t < 4; t++)
        wmma::store_matrix_sync(Ph + w * 16 * 68 + t * 16, acc[t], 68, wmma::mem_row_major);
    __syncthreads();

    {
        const float* rb = g_relbias + h * 4096;
        const float* mk = mask + (size_t)(b & 4095) * 4096;
#pragma unroll
        for (int rr = 0; rr < 16; rr++) {
            int n = w * 16 + rr;
            float l0 = Ph[n * 68 + lane] + rb[n * 64 + lane] + mk[n * 64 + lane];
            float l1 = Ph[n * 68 + lane + 32] + rb[n * 64 + lane + 32] + mk[n * 64 + lane + 32];
            float mx = fmaxf(l0, l1);
#pragma unroll
            for (int o = 16; o; o >>= 1) mx = fmaxf(mx, __shfl_xor_sync(0xffffffffu, mx, o));
            float e0 = __expf(l0 - mx);
            float e1 = __expf(l1 - mx);
            float s = e0 + e1;
#pragma unroll
            for (int o = 16; o; o >>= 1) s += __shfl_xor_sync(0xffffffffu, s, o);
            float inv = 1.0f / s;
            Ph[n * 68 + lane] = rnd32(e0 * inv);
            Ph[n * 68 + lane + 32] = rnd32(e1 * inv);
        }
    }
    __syncthreads();

    FragC xc[2];
#pragma unroll
    for (int t = 0; t < 2; t++) wmma::fill_fragment(xc[t], 0.0f);
#pragma unroll
    for (int k = 0; k < 64; k += 8) {
        FragA a;
        wmma::load_matrix_sync(a, Ph + w * 16 * 68 + k, 68);
#pragma unroll
        for (int t = 0; t < 2; t++) {
            FragBR bf;
            wmma::load_matrix_sync(bf, sV + k * 36 + t * 16, 36);
            wmma::mma_sync(xc[t], a, bf, xc[t]);
        }
    }
    __syncthreads();   // done READING Ph -> overlay x staging

#pragma unroll
    for (int t = 0; t < 2; t++) {
#pragma unroll
        for (int i = 0; i < xc[t].num_elements; i++) xc[t].x[i] = rnd32(xc[t].x[i]);
        wmma::store_matrix_sync(smA + w * 16 * 36 + t * 16, xc[t], 36, wmma::mem_row_major);
    }
    __syncthreads();

    float* xd = g_x + (size_t)b * 8192 + h * 32;
    for (int i = tid; i < 512; i += 128) {
        int r = i >> 3, c4 = i & 7;
        *(float4*)(xd + r * 128 + c4 * 4) = *(const float4*)(smA + r * 36 + c4 * 4);
    }
}

extern "C" void kernel_launch(void* const* d_in, const int* in_sizes, int n_in,
                              void* d_out, int out_size) {
    const float* q          = (const float*)d_in[0];
    const float* kv         = (const float*)d_in[1];
    const float* mask       = (const float*)d_in[2];
    const float* Wq         = (const float*)d_in[3];
    const float* bq         = (const float*)d_in[4];
    const float* Wkv        = (const float*)d_in[5];
    const float* bkv        = (const float*)d_in[6];
    const float* Wo         = (const float*)d_in[7];
    const float* bo         = (const float*)d_in[8];
    const float* bias_table = (const float*)d_in[9];
    float* out = (float*)d_out;

    relbias_kernel<<<64, 256>>>(bias_table);
    roundwts_kernel<<<256, 256>>>(Wq, Wkv, Wo);

    mm3_kernel<<<12288, 512>>>(q, kv, bq, bkv, bo, out, 0);   // qh, k, v projections
    attn_kernel<<<32768, 128>>>(mask);
    mm3_kernel<<<4096, 512>>>(q, kv, bq, bkv, bo, out, 1);    // out-proj
}